// round 15
// baseline (speedup 1.0000x reference)
#include <cuda_runtime.h>
#include <cuda_fp16.h>
#include <stdint.h>
#include <string.h>
#include <math.h>

#define R1   2098176      // (B*N*16 + 32) * 32 rows through m1 MLP
#define NSL  65568        // sl rows
#define NPTS 4096         // B*N
#define BN_EPS 1e-3f

// ------------- device scratch (no allocations allowed) -------------
__device__ float g_sl[NSL*3];
__device__ int   g_idx[NPTS*16];
__device__ float g_xsq[NPTS];             // per-point squared norms
__device__ __half g_z2h[67141632];        // y2 raw fp16, [R1][32] (134MB)
__device__ float g_w2f[32*32+32];         // folded W2 + b2
__device__ float g_w3f[33];               // folded w3[32] + b3
__device__ float g_m2part[64*32*512];     // split-K partials for m2 layer1 (4MB)
__device__ float g_ym2[32*512];
__device__ float g_sm2[512], g_tm2[512];
__device__ float g_w[32*16];              // final BN'd m2 output w
__device__ float g_wcol[16];              // sum_f w[f][c]
__device__ float g_agg[NSL*16];           // raw agg (pre s3/t3)
__device__ float g_s3t3[2];
__device__ float g_F[4194304];            // [4096][1024]
__device__ float g_ymr1[2097152];         // [4096][512]
__device__ float g_wmr1f[512*64+64];      // folded mr W1 + b1
__device__ float g_ymr2[NPTS*64];
__device__ double g_acc[1282];
// acc layout: A1 sum[0..32) sq[32..64); A2 64..128; A3 128,129;
// MR1 sum 130..642 sq 642..1154; MRB sum 1154..1218 sq 1218..1282

// exact mish: v*tanh(softplus(v)) = v*((u+1)^2-1)/((u+1)^2+1), u=e^v.
__device__ __forceinline__ float mishf(float v){
    float u = __expf(fminf(v, 20.0f));
    float p = u + 1.0f;
    float num = fmaf(p, p, -1.0f);
    float den = fmaf(p, p,  1.0f);
    return v * __fdividef(num, den);
}

// ---- packed fp32x2 helpers (FFMA2: PTX-only, 2x fp32 FMA throughput) ----
__device__ __forceinline__ unsigned long long ffma2(unsigned long long a,
                                                    unsigned long long b,
                                                    unsigned long long c){
    unsigned long long d;
    asm("fma.rn.f32x2 %0, %1, %2, %3;" : "=l"(d) : "l"(a), "l"(b), "l"(c));
    return d;
}
__device__ __forceinline__ unsigned long long pk2(float lo, float hi){
    unsigned long long r;
    asm("mov.b64 %0, {%1, %2};" : "=l"(r) : "f"(lo), "f"(hi));
    return r;
}
__device__ __forceinline__ void upk2(unsigned long long v, float& lo, float& hi){
    asm("mov.b64 {%0, %1}, %2;" : "=f"(lo), "=f"(hi) : "l"(v));
}

__global__ void k_zero(){
    for (int i = threadIdx.x; i < 1282; i += 256) g_acc[i] = 0.0;
}

// ---------------- per-point squared norms: one warp per point ----------------
__global__ __launch_bounds__(256) void k_xsq(const float* __restrict__ x){
    int warp = (blockIdx.x*256 + threadIdx.x) >> 5;
    int lane = threadIdx.x & 31;
    float2 v = ((const float2*)(x + (size_t)warp*64))[lane];
    float s = v.x*v.x + v.y*v.y;
    #pragma unroll
    for (int sh=16; sh>0; sh>>=1) s += __shfl_xor_sync(0xffffffffu, s, sh);
    if (lane == 0) g_xsq[warp] = s;
}

// ---------------- kNN: 8 points/block, precomputed norms, FFMA2 dots ----------------
__global__ __launch_bounds__(256) void k_knn(const float* __restrict__ x){
    __shared__ __align__(16) float xn[8][64];
    __shared__ __align__(16) float xm[64][76];
    __shared__ float nsh[64];
    int t = threadIdx.x;
    int wid = t >> 5, lane = t & 31;
    int pt0 = blockIdx.x * 8;
    int b = pt0 >> 9;
    int n0 = pt0 & 511;
    const float* xb = x + (size_t)b*512*64;
    if (t < 128){
        int r = t >> 4, c4 = (t & 15) * 4;
        *(float4*)&xn[r][c4] = *(const float4*)&xb[(size_t)(n0 + r)*64 + c4];
    }
    __syncthreads();
    float sqn = g_xsq[pt0 + wid];
    unsigned long long key[16];
    for (int t8 = 0; t8 < 8; t8++){
        __syncthreads();
        for (int i = t; i < 64*16; i += 256){
            int r = i >> 4, c4 = (i & 15)*4;
            *(float4*)&xm[r][c4] = *(const float4*)&xb[(size_t)(t8*64 + r)*64 + c4];
        }
        if (t < 64) nsh[t] = g_xsq[b*512 + t8*64 + t];
        __syncthreads();
        #pragma unroll
        for (int h=0; h<2; h++){
            int cand = h*32 + lane;
            const ulonglong2* vm = (const ulonglong2*)&xm[cand][0];
            const ulonglong2* vn = (const ulonglong2*)&xn[wid][0];
            unsigned long long acc2 = 0ull;
            #pragma unroll
            for (int q=0;q<16;q++){     // 16 x ulonglong2 = 64 floats (FIX: was 8)
                ulonglong2 a = vm[q];
                ulonglong2 w = vn[q];
                acc2 = ffma2(a.x, w.x, acc2);
                acc2 = ffma2(a.y, w.y, acc2);
            }
            float lo, hi;
            upk2(acc2, lo, hi);
            float dot = lo + hi;
            float d = sqn + nsh[cand] - 2.f*dot;
            unsigned u = __float_as_uint(d);
            u = (u & 0x80000000u) ? ~u : (u | 0x80000000u);
            int m = t8*64 + h*32 + lane;
            key[t8*2+h] = ((unsigned long long)u << 32) | (unsigned)m;
        }
    }
    int pt = pt0 + wid;
    for (int it=0; it<16; it++){
        unsigned long long best = ~0ull;
        #pragma unroll
        for (int j=0;j<16;j++)
            if (key[j] < best) best = key[j];
        #pragma unroll
        for (int s=16;s>0;s>>=1){
            unsigned long long o = __shfl_xor_sync(0xffffffffu, best, s);
            if (o < best) best = o;
        }
        int winm = (int)(best & 0xffffffffu);
        if (lane == 0) g_idx[pt*16 + it] = winm;
        if ((winm & 31) == lane){
            #pragma unroll
            for (int j=0;j<16;j++){
                int m = (j>>1)*64 + (j&1)*32 + lane;
                if (m == winm) key[j] = ~0ull;
            }
        }
    }
}

// ---------------- sl rows ----------------
__global__ void k_sl(const float* __restrict__ xyz, const float* __restrict__ fpts,
                     float c, float s){
    int r = blockIdx.x*256 + threadIdx.x;
    if (r < 65536){
        int k = r >> 4, j = r & 15;
        int b = k >> 9;
        const float* base = xyz + (size_t)b*512*3;
        int i0 = g_idx[k*16];
        int ij = g_idx[k*16+j];
        g_sl[r*3+0] = base[ij*3+0] - base[i0*3+0];
        g_sl[r*3+1] = base[ij*3+1] - base[i0*3+1];
        g_sl[r*3+2] = base[ij*3+2] - base[i0*3+2];
    } else if (r < NSL){
        int i = r - 65536;
        float f0=fpts[i*3], f1=fpts[i*3+1], f2=fpts[i*3+2];
        g_sl[r*3+0] = f0*c - f2*s;
        g_sl[r*3+1] = f1;
        g_sl[r*3+2] = f0*s + f2*c;
    }
}

// ---------------- m2 layer 1 stage A: split-K tiled GEMM [32,4096]@[4096,512] ----------------
__global__ __launch_bounds__(256) void k_m2g(const float* __restrict__ fpw, const float* __restrict__ W){
    __shared__ __align__(16) float Wsh[64][64];
    __shared__ __align__(16) float fsh[32][64];
    int t = threadIdx.x;
    int nb = blockIdx.x, kb = blockIdx.y;
    int n0 = nb*64, k0 = kb*64;
    for (int i = t; i < 64*16; i += 256){
        int kk = i >> 4, c4 = (i & 15) * 4;
        *(float4*)&Wsh[kk][c4] = *(const float4*)&W[(size_t)(k0+kk)*512 + n0 + c4];
    }
    for (int i = t; i < 32*16; i += 256){
        int r = i >> 4, c4 = (i & 15) * 4;
        *(float4*)&fsh[r][c4] = *(const float4*)&fpw[(size_t)r*4096 + k0 + c4];
    }
    __syncthreads();
    int tx = t & 63, ty = t >> 6;
    float acc[8];
    #pragma unroll
    for (int i=0;i<8;i++) acc[i]=0.f;
    #pragma unroll 8
    for (int kk=0;kk<64;kk++){
        float wv = Wsh[kk][tx];
        #pragma unroll
        for (int i=0;i<8;i++)
            acc[i] = fmaf(fsh[ty+i*4][kk], wv, acc[i]);
    }
    #pragma unroll
    for (int i=0;i<8;i++)
        g_m2part[((size_t)kb*32 + ty + i*4)*512 + n0 + tx] = acc[i];
}

// ---------------- m2 layer 1 stage B: sum partials + mish + BN stats ----------------
__global__ __launch_bounds__(128) void k_m2f(const float* __restrict__ bi, const float* __restrict__ g,
                                             const float* __restrict__ be){
    int col = blockIdx.x*128 + threadIdx.x;
    float s=0.f, q=0.f;
    for (int r=0;r<32;r++){
        float a = bi[col];
        for (int kb=0;kb<64;kb++)
            a += g_m2part[((size_t)kb*32 + r)*512 + col];
        float y = mishf(a);
        g_ym2[(size_t)r*512 + col] = y;
        s += y; q = fmaf(y,y,q);
    }
    float mu = s/32.f, var = q/32.f - mu*mu;
    float sv = g[col]*rsqrtf(var+BN_EPS);
    g_sm2[col] = sv;
    g_tm2[col] = be[col] - sv*mu;
}

// ---------------- m2 layer 2 + output BN + wcol (single block) ----------------
__global__ __launch_bounds__(512) void k_m2b(const float* __restrict__ W, const float* __restrict__ bi,
                                             const float* __restrict__ g, const float* __restrict__ be){
    __shared__ float ysh[32][16];
    __shared__ float sc[16], tc[16];
    int t = threadIdx.x;
    int row = t >> 4, c = t & 15;
    float acc = bi[c];
    for (int k=0;k<512;k++){
        float z = fmaf(g_sm2[k], g_ym2[(size_t)row*512+k], g_tm2[k]);
        acc = fmaf(z, W[(size_t)k*16 + c], acc);
    }
    float y = mishf(acc);
    ysh[row][c] = y;
    __syncthreads();
    if (t < 16){
        float S=0.f,Q=0.f;
        for (int r2=0;r2<32;r2++){ float v=ysh[r2][t]; S+=v; Q=fmaf(v,v,Q); }
        float mu=S/32.f, var=Q/32.f-mu*mu;
        float sv = g[t]*rsqrtf(var+BN_EPS);
        sc[t]=sv; tc[t]=be[t]-sv*mu;
    }
    __syncthreads();
    float wb = fmaf(sc[c], y, tc[c]);
    g_w[row*16+c] = wb;
    __syncthreads();
    if (t < 16){
        float S=0.f;
        for (int r2=0;r2<32;r2++) S += g_w[r2*16+t];
        g_wcol[t] = S;
    }
}

// ---------------- m1 pass1: stats of y1 ONLY (no store) ----------------
__global__ __launch_bounds__(256) void k_p1(const float* __restrict__ W1, const float* __restrict__ b1){
    __shared__ float Bsh[32][33];
    __shared__ double red[2][8][32];
    int t = threadIdx.x;
    int kf = t & 31, sub = t >> 5;
    float w0 = W1[kf], w1 = W1[32+kf], w2 = W1[64+kf], bb = b1[kf];
    {
        #pragma unroll
        for (int j=0;j<4;j++){
            int f = sub*4 + j;
            float f0 = g_sl[(65536+f)*3+0];
            float f1 = g_sl[(65536+f)*3+1];
            float f2 = g_sl[(65536+f)*3+2];
            Bsh[f][kf] = fmaf(f2,w2, fmaf(f1,w1, f0*w0));
        }
    }
    __syncthreads();
    float s=0.f, q=0.f;
    #pragma unroll 1
    for (int tile = blockIdx.x; tile < 16392; tile += gridDim.x){
        int rbase = tile*4;
        #pragma unroll
        for (int g=0; g<4; g++){
            float s0 = g_sl[(rbase+g)*3+0];
            float s1 = g_sl[(rbase+g)*3+1];
            float s2 = g_sl[(rbase+g)*3+2];
            float A = fmaf(s2,w2, fmaf(s1,w1, fmaf(s0,w0, bb)));
            #pragma unroll
            for (int j=0;j<4;j++){
                int f = sub*4 + j;
                float y = mishf(A - Bsh[f][kf]);
                s += y; q = fmaf(y,y,q);
            }
        }
    }
    red[0][sub][kf] = (double)s;
    red[1][sub][kf] = (double)q;
    __syncthreads();
    if (t < 32){
        double S=0, Q=0;
        #pragma unroll
        for (int i=0;i<8;i++){ S += red[0][i][t]; Q += red[1][i][t]; }
        atomicAdd(&g_acc[t], S);
        atomicAdd(&g_acc[32+t], Q);
    }
}

// ---------------- fold BN(layer0) into W1 ----------------
__global__ void k_fold1(const float* __restrict__ W, const float* __restrict__ bi,
                        const float* __restrict__ g, const float* __restrict__ be){
    __shared__ float s1[32], t1[32];
    int t = threadIdx.x;
    if (t < 32){
        double mu = g_acc[t] / (double)R1;
        double var = g_acc[32+t] / (double)R1 - mu*mu;
        float sv = g[t] * rsqrtf((float)var + BN_EPS);
        s1[t] = sv;
        t1[t] = be[t] - sv*(float)mu;
    }
    __syncthreads();
    if (t < 32){
        float acc = bi[t];
        for (int j=0;j<32;j++){
            g_w2f[j*32+t] = s1[j]*W[j*32+t];
            acc = fmaf(t1[j], W[j*32+t], acc);
        }
        g_w2f[1024+t] = acc;
    }
}

// ---------------- m1 pass2: RECOMPUTE y1 (A-B) into smem, y2 via FFMA2, store fp16, stats ----------------
__global__ __launch_bounds__(256) void k_p2(const float* __restrict__ W1, const float* __restrict__ b1){
    __shared__ float Bsh[32][33];
    __shared__ __align__(16) float ysh[128][32];
    __shared__ double red[2][8][32];
    int t = threadIdx.x;
    int kf = t & 31, sub = t >> 5;
    float w0 = W1[kf], w1 = W1[32+kf], w2 = W1[64+kf], bb = b1[kf];
    {
        #pragma unroll
        for (int j=0;j<4;j++){
            int f = sub*4 + j;
            float f0 = g_sl[(65536+f)*3+0];
            float f1 = g_sl[(65536+f)*3+1];
            float f2 = g_sl[(65536+f)*3+2];
            Bsh[f][kf] = fmaf(f2,w2, fmaf(f1,w1, f0*w0));
        }
    }
    unsigned long long Wc2[16];
    #pragma unroll
    for (int j=0;j<16;j++)
        Wc2[j] = pk2(g_w2f[(2*j)*32+kf], g_w2f[(2*j+1)*32+kf]);
    float b2 = g_w2f[1024+kf];
    __syncthreads();
    float s=0.f, q=0.f;
    #pragma unroll 1
    for (int tile = blockIdx.x; tile < 16392; tile += gridDim.x){
        size_t base = (size_t)tile*128;
        int rbase = tile*4;
        #pragma unroll
        for (int g=0; g<4; g++){
            float s0 = g_sl[(rbase+g)*3+0];
            float s1 = g_sl[(rbase+g)*3+1];
            float s2 = g_sl[(rbase+g)*3+2];
            float A = fmaf(s2,w2, fmaf(s1,w1, fmaf(s0,w0, bb)));
            #pragma unroll
            for (int j=0;j<4;j++){
                int f = sub*4 + j;
                ysh[g*32 + f][kf] = mishf(A - Bsh[f][kf]);
            }
        }
        __syncthreads();
        #pragma unroll 4
        for (int u=0; u<16; u++){
            int l = u*8+sub;
            unsigned long long acc2 = pk2(b2, 0.0f);
            const ulonglong2* yp = (const ulonglong2*)ysh[l];
            #pragma unroll
            for (int j4=0;j4<8;j4++){
                ulonglong2 pr = yp[j4];
                acc2 = ffma2(pr.x, Wc2[j4*2+0], acc2);
                acc2 = ffma2(pr.y, Wc2[j4*2+1], acc2);
            }
            float lo, hi;
            upk2(acc2, lo, hi);
            float y = mishf(lo + hi);
            g_z2h[(base+l)*32 + kf] = __float2half_rn(y);
            s += y; q = fmaf(y,y,q);
        }
        __syncthreads();
    }
    red[0][sub][kf] = (double)s;
    red[1][sub][kf] = (double)q;
    __syncthreads();
    if (t<32){
        double S=0,Q=0;
        #pragma unroll
        for (int i=0;i<8;i++){S+=red[0][i][t];Q+=red[1][i][t];}
        atomicAdd(&g_acc[64+t], S);
        atomicAdd(&g_acc[96+t], Q);
    }
}

// ---------------- fold BN(layer1) into W2 (32 -> 1) ----------------
__global__ void k_fold2(const float* __restrict__ W, const float* __restrict__ bi,
                        const float* __restrict__ g, const float* __restrict__ be){
    int t = threadIdx.x;   // 32 threads
    double mu = g_acc[64+t] / (double)R1;
    double var = g_acc[96+t]/(double)R1 - mu*mu;
    float sv = g[t]*rsqrtf((float)var + BN_EPS);
    float tv = be[t] - sv*(float)mu;
    float wj = W[t];
    g_w3f[t] = sv*wj;
    float contrib = tv*wj;
    #pragma unroll
    for (int s=16;s>0;s>>=1) contrib += __shfl_xor_sync(0xffffffffu, contrib, s);
    if (t==0) g_w3f[32] = bi[0] + contrib;
}

// ---------------- m1 pass3: h = mish(y2@w3f), stats(h), agg_raw ----------------
__global__ __launch_bounds__(256) void k_p3(){
    __shared__ __align__(16) float ysh[1024];
    __shared__ float wsh[32][16];
    __shared__ double red[2][8];
    int t = threadIdx.x;
    for (int i = t; i < 512; i += 256) wsh[i>>4][i&15] = g_w[i];
    float w3[32];
    #pragma unroll
    for (int j=0;j<32;j++) w3[j] = g_w3f[j];
    float b3 = g_w3f[32];
    float s=0.f,q=0.f;
    __syncthreads();
    #pragma unroll 1
    for (int tile = blockIdx.x; tile < 2049; tile += gridDim.x){
        size_t base = (size_t)tile*1024;
        #pragma unroll
        for (int u=0;u<4;u++){
            int l = u*256 + t;
            const uint4* yp = (const uint4*)(g_z2h + (base+l)*32);
            float acc = b3;
            #pragma unroll
            for (int qq=0;qq<4;qq++){
                uint4 v = yp[qq];
                const half2* hp = (const half2*)&v;
                #pragma unroll
                for (int i=0;i<4;i++){
                    float2 f = __half22float2(hp[i]);
                    acc = fmaf(f.x, w3[qq*8+i*2+0], acc);
                    acc = fmaf(f.y, w3[qq*8+i*2+1], acc);
                }
            }
            float h = mishf(acc);
            ysh[l] = h;
            s += h; q = fmaf(h,h,q);
        }
        __syncthreads();
        #pragma unroll
        for (int u=0;u<2;u++){
            int o = u*256 + t;
            int rg = o >> 4, c = o & 15;
            float acc = 0.f;
            #pragma unroll
            for (int f=0;f<32;f++)
                acc = fmaf(ysh[rg*32+f], wsh[f][c], acc);
            size_t r = (size_t)tile*32 + rg;
            g_agg[r*16 + c] = acc;
        }
        __syncthreads();
    }
    #pragma unroll
    for (int sh=16;sh>0;sh>>=1){
        s += __shfl_xor_sync(0xffffffffu,s,sh);
        q += __shfl_xor_sync(0xffffffffu,q,sh);
    }
    if ((t&31)==0){ red[0][t>>5]=(double)s; red[1][t>>5]=(double)q; }
    __syncthreads();
    if (t==0){
        double S=0,Q=0;
        #pragma unroll
        for(int i=0;i<8;i++){S+=red[0][i];Q+=red[1][i];}
        atomicAdd(&g_acc[128],S); atomicAdd(&g_acc[129],Q);
    }
}

__global__ void k_fold3(const float* __restrict__ g, const float* __restrict__ be){
    double mu = g_acc[128]/(double)R1;
    double var = g_acc[129]/(double)R1 - mu*mu;
    float sv = g[0]*rsqrtf((float)var+BN_EPS);
    g_s3t3[0]=sv; g_s3t3[1]=be[0]-sv*(float)mu;
}

// ---------------- F[k][c][d] = sum_m fur[k][m][c] * wmain[k][m][d] ----------------
__global__ __launch_bounds__(256) void k_F(const float* __restrict__ x){
    int k = blockIdx.x;
    int b = k >> 9;
    __shared__ __align__(16) float fur[16][64];
    __shared__ float wm[16][16];
    int t = threadIdx.x;
    float s3 = g_s3t3[0], t3 = g_s3t3[1];
    {
        int m = t >> 4;
        int c0 = (t & 15) * 4;
        int idx = g_idx[k*16 + m];
        float4 v = *(const float4*)(x + ((size_t)b*512 + idx)*64 + c0);
        *(float4*)&fur[m][c0] = v;
    }
    {
        int m = t >> 4, d = t & 15;
        wm[m][d] = fmaf(s3, g_agg[(size_t)(k*16+m)*16 + d], t3*g_wcol[d]);
    }
    __syncthreads();
    #pragma unroll
    for (int u=0;u<4;u++){
        int o = u*256 + t;
        int c = o >> 4, d = o & 15;
        float acc = 0.f;
        #pragma unroll
        for (int m=0;m<16;m++) acc = fmaf(fur[m][c], wm[m][d], acc);
        g_F[(size_t)k*1024 + o] = acc;
    }
}

// ---------------- MR layer1 GEMM [4096,1024]@[1024,512], 128x64 tile, FFMA2 ----------------
__global__ __launch_bounds__(256) void k_mr1(const float* __restrict__ W, const float* __restrict__ bi){
    __shared__ __align__(16) float As[16][132];
    __shared__ __align__(16) float Bs[16][64];
    __shared__ float rs[16][64], rq[16][64];
    int t = threadIdx.x;
    int tx = t & 15, ty = t >> 4;
    int m0 = blockIdx.y * 128, n0 = blockIdx.x * 64;
    unsigned long long acc2[4][4];
    #pragma unroll
    for (int i=0;i<4;i++)
        #pragma unroll
        for (int j=0;j<4;j++) acc2[i][j] = 0ull;
    for (int k0 = 0; k0 < 1024; k0 += 16){
        #pragma unroll
        for (int jj=0;jj<2;jj++){
            int i = jj*256 + t;
            int m = i >> 2, k4 = (i & 3) * 4;
            float4 a4 = *(const float4*)(g_F + (size_t)(m0+m)*1024 + k0 + k4);
            As[k4+0][m]=a4.x; As[k4+1][m]=a4.y; As[k4+2][m]=a4.z; As[k4+3][m]=a4.w;
        }
        {
            int lb_k = t >> 4, lb_n = (t & 15) * 4;
            *(float4*)&Bs[lb_k][lb_n] = *(const float4*)(W + (size_t)(k0+lb_k)*512 + n0 + lb_n);
        }
        __syncthreads();
        #pragma unroll
        for (int kk=0;kk<16;kk++){
            ulonglong2 a01 = *(const ulonglong2*)&As[kk][ty*8];
            ulonglong2 a23 = *(const ulonglong2*)&As[kk][ty*8+4];
            unsigned long long ap[4] = {a01.x, a01.y, a23.x, a23.y};
            float4 bv = *(const float4*)&Bs[kk][tx*4];
            unsigned long long bd[4] = {pk2(bv.x,bv.x), pk2(bv.y,bv.y),
                                        pk2(bv.z,bv.z), pk2(bv.w,bv.w)};
            #pragma unroll
            for (int i=0;i<4;i++)
                #pragma unroll
                for (int j=0;j<4;j++)
                    acc2[i][j] = ffma2(ap[i], bd[j], acc2[i][j]);
        }
        __syncthreads();
    }
    float bias[4];
    #pragma unroll
    for (int j=0;j<4;j++) bias[j] = bi[n0+tx*4+j];
    float csum[4]={0,0,0,0}, csq[4]={0,0,0,0};
    #pragma unroll
    for (int i=0;i<4;i++){
        float r0[4], r1[4];
        #pragma unroll
        for (int j=0;j<4;j++) upk2(acc2[i][j], r0[j], r1[j]);
        float4 o0, o1;
        float* p0 = &o0.x; float* p1 = &o1.x;
        #pragma unroll
        for (int j=0;j<4;j++){
            float y0 = mishf(r0[j]+bias[j]);
            float y1 = mishf(r1[j]+bias[j]);
            p0[j]=y0; p1[j]=y1;
            csum[j] += y0 + y1;
            csq[j]   = fmaf(y0,y0,csq[j]);
            csq[j]   = fmaf(y1,y1,csq[j]);
        }
        *(float4*)(g_ymr1 + (size_t)(m0+ty*8+2*i+0)*512 + n0+tx*4) = o0;
        *(float4*)(g_ymr1 + (size_t)(m0+ty*8+2*i+1)*512 + n0+tx*4) = o1;
    }
    #pragma unroll
    for (int j=0;j<4;j++){ rs[ty][tx*4+j]=csum[j]; rq[ty][tx*4+j]=csq[j]; }
    __syncthreads();
    if (t < 64){
        float S=0.f,Q=0.f;
        #pragma unroll
        for (int i=0;i<16;i++){ S+=rs[i][t]; Q+=rq[i][t]; }
        atomicAdd(&g_acc[130 + n0 + t], (double)S);
        atomicAdd(&g_acc[642 + n0 + t], (double)Q);
    }
}

// ---------------- fold BN(mr layer0) into mr W1 ----------------
__global__ __launch_bounds__(512) void k_foldmr(const float* __restrict__ W1, const float* __restrict__ b1,
                                                const float* __restrict__ g, const float* __restrict__ be){
    __shared__ float ss[512], tt[512];
    __shared__ float bred[8][64];
    int t = threadIdx.x;
    {
        double mu = g_acc[130+t] / 4096.0;
        double var = g_acc[642+t] / 4096.0 - mu*mu;
        float sv = g[t] * rsqrtf((float)var + BN_EPS);
        ss[t] = sv; tt[t] = be[t] - sv*(float)mu;
    }
    __syncthreads();
    int c = t & 63, jg = t >> 6;
    float bacc = 0.f;
    for (int j = jg*64; j < jg*64+64; j++){
        float w = W1[(size_t)j*64 + c];
        g_wmr1f[(size_t)j*64 + c] = ss[j]*w;
        bacc = fmaf(tt[j], w, bacc);
    }
    bred[jg][c] = bacc;
    __syncthreads();
    if (t < 64){
        float s=0.f;
        #pragma unroll
        for (int i=0;i<8;i++) s += bred[i][t];
        g_wmr1f[512*64 + t] = b1[t] + s;
    }
}

// ---------------- MR layer2 GEMM [4096,512]@[512,64] + mish + stats ----------------
__global__ __launch_bounds__(256) void k_mr2(){
    __shared__ __align__(16) float As[16][64];
    __shared__ __align__(16) float Bs[16][64];
    __shared__ float rs[16][64], rq[16][64];
    int t = threadIdx.x;
    int m0 = blockIdx.x * 64;
    float acc[4][4];
    #pragma unroll
    for (int i=0;i<4;i++)
        #pragma unroll
        for (int j=0;j<4;j++) acc[i][j]=0.f;
    int ty = t >> 4, tx = t & 15;
    int la_m = t >> 2, la_k = (t & 3) * 4;
    int lb_k = t >> 4, lb_n = (t & 15) * 4;
    for (int k0 = 0; k0 < 512; k0 += 16){
        float4 a4 = *(const float4*)(g_ymr1 + (size_t)(m0+la_m)*512 + k0 + la_k);
        float4 b4 = *(const float4*)(g_wmr1f + (size_t)(k0+lb_k)*64 + lb_n);
        As[la_k+0][la_m]=a4.x; As[la_k+1][la_m]=a4.y; As[la_k+2][la_m]=a4.z; As[la_k+3][la_m]=a4.w;
        *(float4*)&Bs[lb_k][lb_n] = b4;
        __syncthreads();
        #pragma unroll
        for (int kk=0;kk<16;kk++){
            float4 av = *(const float4*)&As[kk][ty*4];
            float4 bv = *(const float4*)&Bs[kk][tx*4];
            float a[4]={av.x,av.y,av.z,av.w}, bb[4]={bv.x,bv.y,bv.z,bv.w};
            #pragma unroll
            for (int i=0;i<4;i++)
                #pragma unroll
                for (int j=0;j<4;j++)
                    acc[i][j] = fmaf(a[i], bb[j], acc[i][j]);
        }
        __syncthreads();
    }
    float csum[4]={0,0,0,0}, csq[4]={0,0,0,0};
    #pragma unroll
    for (int i=0;i<4;i++){
        #pragma unroll
        for (int j=0;j<4;j++){
            float y = mishf(acc[i][j] + g_wmr1f[512*64 + tx*4+j]);
            g_ymr2[(size_t)(m0+ty*4+i)*64 + tx*4+j] = y;
            csum[j] += y; csq[j] = fmaf(y,y,csq[j]);
        }
    }
    #pragma unroll
    for (int j=0;j<4;j++){ rs[ty][tx*4+j]=csum[j]; rq[ty][tx*4+j]=csq[j]; }
    __syncthreads();
    if (t < 64){
        float S=0.f,Q=0.f;
        #pragma unroll
        for (int i=0;i<16;i++){ S+=rs[i][t]; Q+=rq[i][t]; }
        atomicAdd(&g_acc[1154 + t], (double)S);
        atomicAdd(&g_acc[1218 + t], (double)Q);
    }
}

// ---------------- final BN apply ----------------
__global__ void k_out(float* __restrict__ out, const float* __restrict__ g, const float* __restrict__ be){
    int i = blockIdx.x*256 + threadIdx.x;
    int c = i & 63;
    double mu = g_acc[1154+c]/4096.0;
    double var = g_acc[1218+c]/4096.0 - mu*mu;
    float sv = g[c]*rsqrtf((float)var+BN_EPS);
    out[i] = fmaf(sv, g_ymr2[i], be[c] - sv*(float)mu);
}

// ---------------- host: jax threefry-2x32 (partitionable) ----------------
static float jax_angle(){
    uint32_t x0=0, x1=0;
    uint32_t ks0=0u, ks1=42u, ks2=0u^42u^0x1BD11BDAu;
    const int Ra[4]={13,15,26,6}, Rb[4]={17,29,16,24};
    x0 += ks0; x1 += ks1;
    uint32_t ks[3]={ks0,ks1,ks2};
    for (int gq=0; gq<5; gq++){
        const int* RR = (gq&1)? Rb : Ra;
        for (int r=0;r<4;r++){
            x0 += x1;
            x1 = (x1<<RR[r])|(x1>>(32-RR[r]));
            x1 ^= x0;
        }
        x0 += ks[(gq+1)%3];
        x1 += ks[(gq+2)%3] + (uint32_t)(gq+1);
    }
    uint32_t bits = x0 ^ x1;   // partitionable path
    uint32_t fb = (bits >> 9) | 0x3f800000u;
    float u;
    memcpy(&u, &fb, 4);
    u -= 1.0f;
    return u * 2.0f * 3.14159274101257324e0f;
}

extern "C" void kernel_launch(void* const* d_in, const int* in_sizes, int n_in,
                              void* d_out, int out_size){
    const float* x    = (const float*)d_in[0];
    const float* xyz  = (const float*)d_in[1];
    const float* fpts = (const float*)d_in[2];
    const float* fpw  = (const float*)d_in[3];
    const float* m1_w0=(const float*)d_in[4],  *m1_b0=(const float*)d_in[5],
               * m1_g0=(const float*)d_in[6],  *m1_be0=(const float*)d_in[7];
    const float* m1_w1=(const float*)d_in[8],  *m1_b1=(const float*)d_in[9],
               * m1_g1=(const float*)d_in[10], *m1_be1=(const float*)d_in[11];
    const float* m1_w2=(const float*)d_in[12], *m1_b2=(const float*)d_in[13],
               * m1_g2=(const float*)d_in[14], *m1_be2=(const float*)d_in[15];
    const float* m2_w0=(const float*)d_in[16], *m2_b0=(const float*)d_in[17],
               * m2_g0=(const float*)d_in[18], *m2_be0=(const float*)d_in[19];
    const float* m2_w1=(const float*)d_in[20], *m2_b1=(const float*)d_in[21],
               * m2_g1=(const float*)d_in[22], *m2_be1=(const float*)d_in[23];
    const float* mr_w0=(const float*)d_in[24], *mr_b0=(const float*)d_in[25],
               * mr_g0=(const float*)d_in[26], *mr_be0=(const float*)d_in[27];
    const float* mr_w1=(const float*)d_in[28], *mr_b1=(const float*)d_in[29],
               * mr_g1=(const float*)d_in[30], *mr_be1=(const float*)d_in[31];
    float* out = (float*)d_out;

    float ang = jax_angle();
    float cc = (float)cos((double)ang);
    float ss = (float)sin((double)ang);

    k_zero<<<1,256>>>();
    k_xsq<<<512,256>>>(x);
    k_m2g<<<dim3(8,64),256>>>(fpw, m2_w0);
    k_knn<<<512,256>>>(x);                 // capture slot (launch idx 3)
    k_sl<<<(NSL+255)/256,256>>>(xyz, fpts, cc, ss);
    k_p1<<<2048,256>>>(m1_w0, m1_b0);
    k_fold1<<<1,32>>>(m1_w1, m1_b1, m1_g0, m1_be0);
    k_p2<<<2048,256>>>(m1_w0, m1_b0);
    k_fold2<<<1,32>>>(m1_w2, m1_b2, m1_g1, m1_be1);
    k_m2f<<<4,128>>>(m2_b0, m2_g0, m2_be0);
    k_m2b<<<1,512>>>(m2_w1, m2_b1, m2_g1, m2_be1);
    k_p3<<<1024,256>>>();
    k_fold3<<<1,1>>>(m1_g2, m1_be2);
    k_F<<<4096,256>>>(x);
    k_mr1<<<dim3(8,32),256>>>(mr_w0, mr_b0);
    k_foldmr<<<1,512>>>(mr_w1, mr_b1, mr_g0, mr_be0);
    k_mr2<<<64,256>>>();
    k_out<<<1024,256>>>(out, mr_g1, mr_be1);
}

// round 16
// speedup vs baseline: 1.3266x; 1.3266x over previous
#include <cuda_runtime.h>
#include <cuda_fp16.h>
#include <stdint.h>
#include <string.h>
#include <math.h>

#define R1   2098176      // (B*N*16 + 32) * 32 rows through m1 MLP
#define NSL  65568        // sl rows
#define NPTS 4096         // B*N
#define BN_EPS 1e-3f

// ------------- device scratch (no allocations allowed) -------------
__device__ float g_sl[NSL*3];
__device__ int   g_idx[NPTS*16];
__device__ float g_xsq[NPTS];             // per-point squared norms
__device__ __half g_z2h[67141632];        // y2 raw fp16, [R1][32] (134MB)
__device__ float g_m2part[64*32*512];     // split-K partials for m2 layer1 (4MB)
__device__ float g_ym2[32*512];
__device__ float g_sm2[512], g_tm2[512];
__device__ float g_w[32*16];              // final BN'd m2 output w
__device__ float g_wcol[16];              // sum_f w[f][c]
__device__ float g_agg[NSL*16];           // raw agg (pre s3/t3)
__device__ float g_F[4194304];            // [4096][1024]
__device__ float g_ymr1[2097152];         // [4096][512]
__device__ float g_wmr1f[512*64+64];      // folded mr W1 + b1
__device__ float g_ymr2[NPTS*64];
__device__ double g_acc[1282];
// acc layout: A1 sum[0..32) sq[32..64); A2 64..128; A3 128,129;
// MR1 sum 130..642 sq 642..1154; MRB sum 1154..1218 sq 1218..1282

// exact mish: v*tanh(softplus(v)) = v*((u+1)^2-1)/((u+1)^2+1), u=e^v.
__device__ __forceinline__ float mishf(float v){
    float u = __expf(fminf(v, 20.0f));
    float p = u + 1.0f;
    float num = fmaf(p, p, -1.0f);
    float den = fmaf(p, p,  1.0f);
    return v * __fdividef(num, den);
}

// ---- packed fp32x2 helpers (FFMA2: PTX-only, 2x fp32 FMA throughput) ----
__device__ __forceinline__ unsigned long long ffma2(unsigned long long a,
                                                    unsigned long long b,
                                                    unsigned long long c){
    unsigned long long d;
    asm("fma.rn.f32x2 %0, %1, %2, %3;" : "=l"(d) : "l"(a), "l"(b), "l"(c));
    return d;
}
__device__ __forceinline__ unsigned long long pk2(float lo, float hi){
    unsigned long long r;
    asm("mov.b64 %0, {%1, %2};" : "=l"(r) : "f"(lo), "f"(hi));
    return r;
}
__device__ __forceinline__ void upk2(unsigned long long v, float& lo, float& hi){
    asm("mov.b64 {%0, %1}, %2;" : "=f"(lo), "=f"(hi) : "l"(v));
}

__global__ void k_zero(){
    for (int i = threadIdx.x; i < 1282; i += 256) g_acc[i] = 0.0;
}

// ---------------- per-point squared norms: one warp per point ----------------
__global__ __launch_bounds__(256) void k_xsq(const float* __restrict__ x){
    int warp = (blockIdx.x*256 + threadIdx.x) >> 5;
    int lane = threadIdx.x & 31;
    float2 v = ((const float2*)(x + (size_t)warp*64))[lane];
    float s = v.x*v.x + v.y*v.y;
    #pragma unroll
    for (int sh=16; sh>0; sh>>=1) s += __shfl_xor_sync(0xffffffffu, s, sh);
    if (lane == 0) g_xsq[warp] = s;
}

// ---------------- kNN: 8 points/block, REDUX top-16 selection ----------------
__global__ __launch_bounds__(256) void k_knn(const float* __restrict__ x){
    __shared__ __align__(16) float xn[8][64];
    __shared__ __align__(16) float xm[64][76];
    __shared__ float nsh[64];
    int t = threadIdx.x;
    int wid = t >> 5, lane = t & 31;
    int pt0 = blockIdx.x * 8;
    int b = pt0 >> 9;
    int n0 = pt0 & 511;
    const float* xb = x + (size_t)b*512*64;
    if (t < 128){
        int r = t >> 4, c4 = (t & 15) * 4;
        *(float4*)&xn[r][c4] = *(const float4*)&xb[(size_t)(n0 + r)*64 + c4];
    }
    __syncthreads();
    float sqn = g_xsq[pt0 + wid];
    unsigned kd[16];
    for (int t8 = 0; t8 < 8; t8++){
        __syncthreads();
        for (int i = t; i < 64*16; i += 256){
            int r = i >> 4, c4 = (i & 15)*4;
            *(float4*)&xm[r][c4] = *(const float4*)&xb[(size_t)(t8*64 + r)*64 + c4];
        }
        if (t < 64) nsh[t] = g_xsq[b*512 + t8*64 + t];
        __syncthreads();
        #pragma unroll
        for (int h=0; h<2; h++){
            int cand = h*32 + lane;
            const ulonglong2* vm = (const ulonglong2*)&xm[cand][0];
            const ulonglong2* vn = (const ulonglong2*)&xn[wid][0];
            unsigned long long acc2 = 0ull;
            #pragma unroll
            for (int q=0;q<16;q++){     // 16 x ulonglong2 = 64 floats
                ulonglong2 a = vm[q];
                ulonglong2 w = vn[q];
                acc2 = ffma2(a.x, w.x, acc2);
                acc2 = ffma2(a.y, w.y, acc2);
            }
            float lo, hi;
            upk2(acc2, lo, hi);
            float dot = lo + hi;
            float d = sqn + nsh[cand] - 2.f*dot;
            unsigned u = __float_as_uint(d);
            u = (u & 0x80000000u) ? ~u : (u | 0x80000000u);
            kd[t8*2+h] = u;
        }
    }
    int pt = pt0 + wid;
    for (int it=0; it<16; it++){
        unsigned bd = 0xFFFFFFFFu;
        #pragma unroll
        for (int j=0;j<16;j++) bd = umin(bd, kd[j]);
        unsigned wmin = __reduce_min_sync(0xffffffffu, bd);
        unsigned mloc = 0xFFFFFFFFu;
        #pragma unroll
        for (int j=15;j>=0;j--){   // descending: final overwrite = smallest m
            unsigned m = ((unsigned)(j>>1)<<6) | ((unsigned)(j&1)<<5) | (unsigned)lane;
            if (kd[j] == wmin) mloc = m;
        }
        unsigned minm = __reduce_min_sync(0xffffffffu, mloc);
        if (lane == 0) g_idx[pt*16 + it] = (int)minm;
        if ((minm & 31u) == (unsigned)lane){
            int j = (int)(((minm >> 6) << 1) | ((minm >> 5) & 1u));
            kd[j] = 0xFFFFFFFFu;
        }
    }
}

// ---------------- sl rows ----------------
__global__ void k_sl(const float* __restrict__ xyz, const float* __restrict__ fpts,
                     float c, float s){
    int r = blockIdx.x*256 + threadIdx.x;
    if (r < 65536){
        int k = r >> 4, j = r & 15;
        int b = k >> 9;
        const float* base = xyz + (size_t)b*512*3;
        int i0 = g_idx[k*16];
        int ij = g_idx[k*16+j];
        g_sl[r*3+0] = base[ij*3+0] - base[i0*3+0];
        g_sl[r*3+1] = base[ij*3+1] - base[i0*3+1];
        g_sl[r*3+2] = base[ij*3+2] - base[i0*3+2];
    } else if (r < NSL){
        int i = r - 65536;
        float f0=fpts[i*3], f1=fpts[i*3+1], f2=fpts[i*3+2];
        g_sl[r*3+0] = f0*c - f2*s;
        g_sl[r*3+1] = f1;
        g_sl[r*3+2] = f0*s + f2*c;
    }
}

// ---------------- m2 layer 1 stage A: split-K tiled GEMM [32,4096]@[4096,512] ----------------
__global__ __launch_bounds__(256) void k_m2g(const float* __restrict__ fpw, const float* __restrict__ W){
    __shared__ __align__(16) float Wsh[64][64];
    __shared__ __align__(16) float fsh[32][64];
    int t = threadIdx.x;
    int nb = blockIdx.x, kb = blockIdx.y;
    int n0 = nb*64, k0 = kb*64;
    for (int i = t; i < 64*16; i += 256){
        int kk = i >> 4, c4 = (i & 15) * 4;
        *(float4*)&Wsh[kk][c4] = *(const float4*)&W[(size_t)(k0+kk)*512 + n0 + c4];
    }
    for (int i = t; i < 32*16; i += 256){
        int r = i >> 4, c4 = (i & 15) * 4;
        *(float4*)&fsh[r][c4] = *(const float4*)&fpw[(size_t)r*4096 + k0 + c4];
    }
    __syncthreads();
    int tx = t & 63, ty = t >> 6;
    float acc[8];
    #pragma unroll
    for (int i=0;i<8;i++) acc[i]=0.f;
    #pragma unroll 8
    for (int kk=0;kk<64;kk++){
        float wv = Wsh[kk][tx];
        #pragma unroll
        for (int i=0;i<8;i++)
            acc[i] = fmaf(fsh[ty+i*4][kk], wv, acc[i]);
    }
    #pragma unroll
    for (int i=0;i<8;i++)
        g_m2part[((size_t)kb*32 + ty + i*4)*512 + n0 + tx] = acc[i];
}

// ---------------- m2 layer 1 stage B: sum partials + mish + BN stats ----------------
__global__ __launch_bounds__(128) void k_m2f(const float* __restrict__ bi, const float* __restrict__ g,
                                             const float* __restrict__ be){
    int col = blockIdx.x*128 + threadIdx.x;
    float s=0.f, q=0.f;
    for (int r=0;r<32;r++){
        float a = bi[col];
        for (int kb=0;kb<64;kb++)
            a += g_m2part[((size_t)kb*32 + r)*512 + col];
        float y = mishf(a);
        g_ym2[(size_t)r*512 + col] = y;
        s += y; q = fmaf(y,y,q);
    }
    float mu = s/32.f, var = q/32.f - mu*mu;
    float sv = g[col]*rsqrtf(var+BN_EPS);
    g_sm2[col] = sv;
    g_tm2[col] = be[col] - sv*mu;
}

// ---------------- m2 layer 2 + output BN + wcol (single block) ----------------
__global__ __launch_bounds__(512) void k_m2b(const float* __restrict__ W, const float* __restrict__ bi,
                                             const float* __restrict__ g, const float* __restrict__ be){
    __shared__ float ysh[32][16];
    __shared__ float sc[16], tc[16];
    int t = threadIdx.x;
    int row = t >> 4, c = t & 15;
    float acc = bi[c];
    for (int k=0;k<512;k++){
        float z = fmaf(g_sm2[k], g_ym2[(size_t)row*512+k], g_tm2[k]);
        acc = fmaf(z, W[(size_t)k*16 + c], acc);
    }
    float y = mishf(acc);
    ysh[row][c] = y;
    __syncthreads();
    if (t < 16){
        float S=0.f,Q=0.f;
        for (int r2=0;r2<32;r2++){ float v=ysh[r2][t]; S+=v; Q=fmaf(v,v,Q); }
        float mu=S/32.f, var=Q/32.f-mu*mu;
        float sv = g[t]*rsqrtf(var+BN_EPS);
        sc[t]=sv; tc[t]=be[t]-sv*mu;
    }
    __syncthreads();
    float wb = fmaf(sc[c], y, tc[c]);
    g_w[row*16+c] = wb;
    __syncthreads();
    if (t < 16){
        float S=0.f;
        for (int r2=0;r2<32;r2++) S += g_w[r2*16+t];
        g_wcol[t] = S;
    }
}

// ---------------- m1 pass1: stats of y1 ONLY (no store) ----------------
__global__ __launch_bounds__(256) void k_p1(const float* __restrict__ W1, const float* __restrict__ b1){
    __shared__ float Bsh[32][33];
    __shared__ double red[2][8][32];
    int t = threadIdx.x;
    int kf = t & 31, sub = t >> 5;
    float w0 = W1[kf], w1 = W1[32+kf], w2 = W1[64+kf], bb = b1[kf];
    {
        #pragma unroll
        for (int j=0;j<4;j++){
            int f = sub*4 + j;
            float f0 = g_sl[(65536+f)*3+0];
            float f1 = g_sl[(65536+f)*3+1];
            float f2 = g_sl[(65536+f)*3+2];
            Bsh[f][kf] = fmaf(f2,w2, fmaf(f1,w1, f0*w0));
        }
    }
    __syncthreads();
    float s=0.f, q=0.f;
    #pragma unroll 1
    for (int tile = blockIdx.x; tile < 16392; tile += gridDim.x){
        int rbase = tile*4;
        #pragma unroll
        for (int g=0; g<4; g++){
            float s0 = g_sl[(rbase+g)*3+0];
            float s1 = g_sl[(rbase+g)*3+1];
            float s2 = g_sl[(rbase+g)*3+2];
            float A = fmaf(s2,w2, fmaf(s1,w1, fmaf(s0,w0, bb)));
            #pragma unroll
            for (int j=0;j<4;j++){
                int f = sub*4 + j;
                float y = mishf(A - Bsh[f][kf]);
                s += y; q = fmaf(y,y,q);
            }
        }
    }
    red[0][sub][kf] = (double)s;
    red[1][sub][kf] = (double)q;
    __syncthreads();
    if (t < 32){
        double S=0, Q=0;
        #pragma unroll
        for (int i=0;i<8;i++){ S += red[0][i][t]; Q += red[1][i][t]; }
        atomicAdd(&g_acc[t], S);
        atomicAdd(&g_acc[32+t], Q);
    }
}

// ---------------- m1 pass2 (fold1 merged): recompute y1, y2 via FFMA2, store fp16, stats ----------------
__global__ __launch_bounds__(256) void k_p2(const float* __restrict__ W1, const float* __restrict__ b1,
                                            const float* __restrict__ W2, const float* __restrict__ b2v,
                                            const float* __restrict__ g0, const float* __restrict__ be0){
    __shared__ float Bsh[32][33];
    __shared__ float s1s[32], t1s[32];
    __shared__ __align__(16) float ysh[128][32];
    __shared__ double red[2][8][32];
    int t = threadIdx.x;
    int kf = t & 31, sub = t >> 5;
    float w0 = W1[kf], w1 = W1[32+kf], w2 = W1[64+kf], bb = b1[kf];
    if (t < 32){
        double mu = g_acc[t] / (double)R1;
        double var = g_acc[32+t] / (double)R1 - mu*mu;
        float sv = g0[t] * rsqrtf((float)var + BN_EPS);
        s1s[t] = sv;
        t1s[t] = be0[t] - sv*(float)mu;
    }
    {
        #pragma unroll
        for (int j=0;j<4;j++){
            int f = sub*4 + j;
            float f0 = g_sl[(65536+f)*3+0];
            float f1 = g_sl[(65536+f)*3+1];
            float f2 = g_sl[(65536+f)*3+2];
            Bsh[f][kf] = fmaf(f2,w2, fmaf(f1,w1, f0*w0));
        }
    }
    __syncthreads();
    unsigned long long Wc2[16];
    float b2 = b2v[kf];
    #pragma unroll
    for (int j=0;j<16;j++){
        float wa = W2[(2*j)*32+kf];
        float wb = W2[(2*j+1)*32+kf];
        Wc2[j] = pk2(s1s[2*j]*wa, s1s[2*j+1]*wb);
        b2 = fmaf(t1s[2*j],   wa, b2);
        b2 = fmaf(t1s[2*j+1], wb, b2);
    }
    float s=0.f, q=0.f;
    #pragma unroll 1
    for (int tile = blockIdx.x; tile < 16392; tile += gridDim.x){
        size_t base = (size_t)tile*128;
        int rbase = tile*4;
        #pragma unroll
        for (int g=0; g<4; g++){
            float s0 = g_sl[(rbase+g)*3+0];
            float s1 = g_sl[(rbase+g)*3+1];
            float s2 = g_sl[(rbase+g)*3+2];
            float A = fmaf(s2,w2, fmaf(s1,w1, fmaf(s0,w0, bb)));
            #pragma unroll
            for (int j=0;j<4;j++){
                int f = sub*4 + j;
                ysh[g*32 + f][kf] = mishf(A - Bsh[f][kf]);
            }
        }
        __syncthreads();
        #pragma unroll 4
        for (int u=0; u<16; u++){
            int l = u*8+sub;
            unsigned long long acc2 = pk2(b2, 0.0f);
            const ulonglong2* yp = (const ulonglong2*)ysh[l];
            #pragma unroll
            for (int j4=0;j4<8;j4++){
                ulonglong2 pr = yp[j4];
                acc2 = ffma2(pr.x, Wc2[j4*2+0], acc2);
                acc2 = ffma2(pr.y, Wc2[j4*2+1], acc2);
            }
            float lo, hi;
            upk2(acc2, lo, hi);
            float y = mishf(lo + hi);
            g_z2h[(base+l)*32 + kf] = __float2half_rn(y);
            s += y; q = fmaf(y,y,q);
        }
        __syncthreads();
    }
    red[0][sub][kf] = (double)s;
    red[1][sub][kf] = (double)q;
    __syncthreads();
    if (t<32){
        double S=0,Q=0;
        #pragma unroll
        for (int i=0;i<8;i++){S+=red[0][i][t];Q+=red[1][i][t];}
        atomicAdd(&g_acc[64+t], S);
        atomicAdd(&g_acc[96+t], Q);
    }
}

// ---------------- m1 pass3 (fold2 merged): h = mish(y2@w3f), stats(h), agg_raw ----------------
__global__ __launch_bounds__(256) void k_p3(const float* __restrict__ W3, const float* __restrict__ b3v,
                                            const float* __restrict__ g1, const float* __restrict__ be1){
    __shared__ __align__(16) float ysh[1024];
    __shared__ float wsh[32][16];
    __shared__ float w3s[32];
    __shared__ float b3s;
    __shared__ double red[2][8];
    int t = threadIdx.x;
    for (int i = t; i < 512; i += 256) wsh[i>>4][i&15] = g_w[i];
    if (t < 32){
        double mu = g_acc[64+t] / (double)R1;
        double var = g_acc[96+t]/(double)R1 - mu*mu;
        float sv = g1[t]*rsqrtf((float)var + BN_EPS);
        float tv = be1[t] - sv*(float)mu;
        float wj = W3[t];
        w3s[t] = sv*wj;
        float contrib = tv*wj;
        #pragma unroll
        for (int sh=16;sh>0;sh>>=1) contrib += __shfl_xor_sync(0xffffffffu, contrib, sh);
        if (t==0) b3s = b3v[0] + contrib;
    }
    __syncthreads();
    float w3[32];
    #pragma unroll
    for (int j=0;j<32;j++) w3[j] = w3s[j];
    float b3 = b3s;
    float s=0.f,q=0.f;
    #pragma unroll 1
    for (int tile = blockIdx.x; tile < 2049; tile += gridDim.x){
        size_t base = (size_t)tile*1024;
        #pragma unroll
        for (int u=0;u<4;u++){
            int l = u*256 + t;
            const uint4* yp = (const uint4*)(g_z2h + (base+l)*32);
            float acc = b3;
            #pragma unroll
            for (int qq=0;qq<4;qq++){
                uint4 v = yp[qq];
                const half2* hp = (const half2*)&v;
                #pragma unroll
                for (int i=0;i<4;i++){
                    float2 f = __half22float2(hp[i]);
                    acc = fmaf(f.x, w3[qq*8+i*2+0], acc);
                    acc = fmaf(f.y, w3[qq*8+i*2+1], acc);
                }
            }
            float h = mishf(acc);
            ysh[l] = h;
            s += h; q = fmaf(h,h,q);
        }
        __syncthreads();
        #pragma unroll
        for (int u=0;u<2;u++){
            int o = u*256 + t;
            int rg = o >> 4, c = o & 15;
            float acc = 0.f;
            #pragma unroll
            for (int f=0;f<32;f++)
                acc = fmaf(ysh[rg*32+f], wsh[f][c], acc);
            size_t r = (size_t)tile*32 + rg;
            g_agg[r*16 + c] = acc;
        }
        __syncthreads();
    }
    #pragma unroll
    for (int sh=16;sh>0;sh>>=1){
        s += __shfl_xor_sync(0xffffffffu,s,sh);
        q += __shfl_xor_sync(0xffffffffu,q,sh);
    }
    if ((t&31)==0){ red[0][t>>5]=(double)s; red[1][t>>5]=(double)q; }
    __syncthreads();
    if (t==0){
        double S=0,Q=0;
        #pragma unroll
        for(int i=0;i<8;i++){S+=red[0][i];Q+=red[1][i];}
        atomicAdd(&g_acc[128],S); atomicAdd(&g_acc[129],Q);
    }
}

// ---------------- F (fold3 merged): F[k][c][d] = sum_m fur[k][m][c] * wmain[k][m][d] ----------------
__global__ __launch_bounds__(256) void k_F(const float* __restrict__ x,
                                           const float* __restrict__ g2, const float* __restrict__ be2){
    int k = blockIdx.x;
    int b = k >> 9;
    __shared__ __align__(16) float fur[16][64];
    __shared__ float wm[16][16];
    __shared__ float s3t3s[2];
    int t = threadIdx.x;
    if (t == 0){
        double mu = g_acc[128]/(double)R1;
        double var = g_acc[129]/(double)R1 - mu*mu;
        float sv = g2[0]*rsqrtf((float)var+BN_EPS);
        s3t3s[0]=sv; s3t3s[1]=be2[0]-sv*(float)mu;
    }
    {
        int m = t >> 4;
        int c0 = (t & 15) * 4;
        int idx = g_idx[k*16 + m];
        float4 v = *(const float4*)(x + ((size_t)b*512 + idx)*64 + c0);
        *(float4*)&fur[m][c0] = v;
    }
    __syncthreads();
    float s3 = s3t3s[0], t3 = s3t3s[1];
    {
        int m = t >> 4, d = t & 15;
        wm[m][d] = fmaf(s3, g_agg[(size_t)(k*16+m)*16 + d], t3*g_wcol[d]);
    }
    __syncthreads();
    #pragma unroll
    for (int u=0;u<4;u++){
        int o = u*256 + t;
        int c = o >> 4, d = o & 15;
        float acc = 0.f;
        #pragma unroll
        for (int m=0;m<16;m++) acc = fmaf(fur[m][c], wm[m][d], acc);
        g_F[(size_t)k*1024 + o] = acc;
    }
}

// ---------------- MR layer1 GEMM [4096,1024]@[1024,512], 128x64 tile, FFMA2 ----------------
__global__ __launch_bounds__(256) void k_mr1(const float* __restrict__ W, const float* __restrict__ bi){
    __shared__ __align__(16) float As[16][132];
    __shared__ __align__(16) float Bs[16][64];
    __shared__ float rs[16][64], rq[16][64];
    int t = threadIdx.x;
    int tx = t & 15, ty = t >> 4;
    int m0 = blockIdx.y * 128, n0 = blockIdx.x * 64;
    unsigned long long acc2[4][4];
    #pragma unroll
    for (int i=0;i<4;i++)
        #pragma unroll
        for (int j=0;j<4;j++) acc2[i][j] = 0ull;
    for (int k0 = 0; k0 < 1024; k0 += 16){
        #pragma unroll
        for (int jj=0;jj<2;jj++){
            int i = jj*256 + t;
            int m = i >> 2, k4 = (i & 3) * 4;
            float4 a4 = *(const float4*)(g_F + (size_t)(m0+m)*1024 + k0 + k4);
            As[k4+0][m]=a4.x; As[k4+1][m]=a4.y; As[k4+2][m]=a4.z; As[k4+3][m]=a4.w;
        }
        {
            int lb_k = t >> 4, lb_n = (t & 15) * 4;
            *(float4*)&Bs[lb_k][lb_n] = *(const float4*)(W + (size_t)(k0+lb_k)*512 + n0 + lb_n);
        }
        __syncthreads();
        #pragma unroll
        for (int kk=0;kk<16;kk++){
            ulonglong2 a01 = *(const ulonglong2*)&As[kk][ty*8];
            ulonglong2 a23 = *(const ulonglong2*)&As[kk][ty*8+4];
            unsigned long long ap[4] = {a01.x, a01.y, a23.x, a23.y};
            float4 bv = *(const float4*)&Bs[kk][tx*4];
            unsigned long long bd[4] = {pk2(bv.x,bv.x), pk2(bv.y,bv.y),
                                        pk2(bv.z,bv.z), pk2(bv.w,bv.w)};
            #pragma unroll
            for (int i=0;i<4;i++)
                #pragma unroll
                for (int j=0;j<4;j++)
                    acc2[i][j] = ffma2(ap[i], bd[j], acc2[i][j]);
        }
        __syncthreads();
    }
    float bias[4];
    #pragma unroll
    for (int j=0;j<4;j++) bias[j] = bi[n0+tx*4+j];
    float csum[4]={0,0,0,0}, csq[4]={0,0,0,0};
    #pragma unroll
    for (int i=0;i<4;i++){
        float r0[4], r1[4];
        #pragma unroll
        for (int j=0;j<4;j++) upk2(acc2[i][j], r0[j], r1[j]);
        float4 o0, o1;
        float* p0 = &o0.x; float* p1 = &o1.x;
        #pragma unroll
        for (int j=0;j<4;j++){
            float y0 = mishf(r0[j]+bias[j]);
            float y1 = mishf(r1[j]+bias[j]);
            p0[j]=y0; p1[j]=y1;
            csum[j] += y0 + y1;
            csq[j]   = fmaf(y0,y0,csq[j]);
            csq[j]   = fmaf(y1,y1,csq[j]);
        }
        *(float4*)(g_ymr1 + (size_t)(m0+ty*8+2*i+0)*512 + n0+tx*4) = o0;
        *(float4*)(g_ymr1 + (size_t)(m0+ty*8+2*i+1)*512 + n0+tx*4) = o1;
    }
    #pragma unroll
    for (int j=0;j<4;j++){ rs[ty][tx*4+j]=csum[j]; rq[ty][tx*4+j]=csq[j]; }
    __syncthreads();
    if (t < 64){
        float S=0.f,Q=0.f;
        #pragma unroll
        for (int i=0;i<16;i++){ S+=rs[i][t]; Q+=rq[i][t]; }
        atomicAdd(&g_acc[130 + n0 + t], (double)S);
        atomicAdd(&g_acc[642 + n0 + t], (double)Q);
    }
}

// ---------------- fold BN(mr layer0) into mr W1 ----------------
__global__ __launch_bounds__(512) void k_foldmr(const float* __restrict__ W1, const float* __restrict__ b1,
                                                const float* __restrict__ g, const float* __restrict__ be){
    __shared__ float ss[512], tt[512];
    __shared__ float bred[8][64];
    int t = threadIdx.x;
    {
        double mu = g_acc[130+t] / 4096.0;
        double var = g_acc[642+t] / 4096.0 - mu*mu;
        float sv = g[t] * rsqrtf((float)var + BN_EPS);
        ss[t] = sv; tt[t] = be[t] - sv*(float)mu;
    }
    __syncthreads();
    int c = t & 63, jg = t >> 6;
    float bacc = 0.f;
    for (int j = jg*64; j < jg*64+64; j++){
        float w = W1[(size_t)j*64 + c];
        g_wmr1f[(size_t)j*64 + c] = ss[j]*w;
        bacc = fmaf(tt[j], w, bacc);
    }
    bred[jg][c] = bacc;
    __syncthreads();
    if (t < 64){
        float s=0.f;
        #pragma unroll
        for (int i=0;i<8;i++) s += bred[i][t];
        g_wmr1f[512*64 + t] = b1[t] + s;
    }
}

// ---------------- MR layer2 GEMM [4096,512]@[512,64] + mish + stats ----------------
__global__ __launch_bounds__(256) void k_mr2(){
    __shared__ __align__(16) float As[16][64];
    __shared__ __align__(16) float Bs[16][64];
    __shared__ float rs[16][64], rq[16][64];
    int t = threadIdx.x;
    int m0 = blockIdx.x * 64;
    float acc[4][4];
    #pragma unroll
    for (int i=0;i<4;i++)
        #pragma unroll
        for (int j=0;j<4;j++) acc[i][j]=0.f;
    int ty = t >> 4, tx = t & 15;
    int la_m = t >> 2, la_k = (t & 3) * 4;
    int lb_k = t >> 4, lb_n = (t & 15) * 4;
    for (int k0 = 0; k0 < 512; k0 += 16){
        float4 a4 = *(const float4*)(g_ymr1 + (size_t)(m0+la_m)*512 + k0 + la_k);
        float4 b4 = *(const float4*)(g_wmr1f + (size_t)(k0+lb_k)*64 + lb_n);
        As[la_k+0][la_m]=a4.x; As[la_k+1][la_m]=a4.y; As[la_k+2][la_m]=a4.z; As[la_k+3][la_m]=a4.w;
        *(float4*)&Bs[lb_k][lb_n] = b4;
        __syncthreads();
        #pragma unroll
        for (int kk=0;kk<16;kk++){
            float4 av = *(const float4*)&As[kk][ty*4];
            float4 bv = *(const float4*)&Bs[kk][tx*4];
            float a[4]={av.x,av.y,av.z,av.w}, bb[4]={bv.x,bv.y,bv.z,bv.w};
            #pragma unroll
            for (int i=0;i<4;i++)
                #pragma unroll
                for (int j=0;j<4;j++)
                    acc[i][j] = fmaf(a[i], bb[j], acc[i][j]);
        }
        __syncthreads();
    }
    float csum[4]={0,0,0,0}, csq[4]={0,0,0,0};
    #pragma unroll
    for (int i=0;i<4;i++){
        #pragma unroll
        for (int j=0;j<4;j++){
            float y = mishf(acc[i][j] + g_wmr1f[512*64 + tx*4+j]);
            g_ymr2[(size_t)(m0+ty*4+i)*64 + tx*4+j] = y;
            csum[j] += y; csq[j] = fmaf(y,y,csq[j]);
        }
    }
    #pragma unroll
    for (int j=0;j<4;j++){ rs[ty][tx*4+j]=csum[j]; rq[ty][tx*4+j]=csq[j]; }
    __syncthreads();
    if (t < 64){
        float S=0.f,Q=0.f;
        #pragma unroll
        for (int i=0;i<16;i++){ S+=rs[i][t]; Q+=rq[i][t]; }
        atomicAdd(&g_acc[1154 + t], (double)S);
        atomicAdd(&g_acc[1218 + t], (double)Q);
    }
}

// ---------------- final BN apply ----------------
__global__ void k_out(float* __restrict__ out, const float* __restrict__ g, const float* __restrict__ be){
    int i = blockIdx.x*256 + threadIdx.x;
    int c = i & 63;
    double mu = g_acc[1154+c]/4096.0;
    double var = g_acc[1218+c]/4096.0 - mu*mu;
    float sv = g[c]*rsqrtf((float)var+BN_EPS);
    out[i] = fmaf(sv, g_ymr2[i], be[c] - sv*(float)mu);
}

// ---------------- host: jax threefry-2x32 (partitionable) ----------------
static float jax_angle(){
    uint32_t x0=0, x1=0;
    uint32_t ks0=0u, ks1=42u, ks2=0u^42u^0x1BD11BDAu;
    const int Ra[4]={13,15,26,6}, Rb[4]={17,29,16,24};
    x0 += ks0; x1 += ks1;
    uint32_t ks[3]={ks0,ks1,ks2};
    for (int gq=0; gq<5; gq++){
        const int* RR = (gq&1)? Rb : Ra;
        for (int r=0;r<4;r++){
            x0 += x1;
            x1 = (x1<<RR[r])|(x1>>(32-RR[r]));
            x1 ^= x0;
        }
        x0 += ks[(gq+1)%3];
        x1 += ks[(gq+2)%3] + (uint32_t)(gq+1);
    }
    uint32_t bits = x0 ^ x1;   // partitionable path
    uint32_t fb = (bits >> 9) | 0x3f800000u;
    float u;
    memcpy(&u, &fb, 4);
    u -= 1.0f;
    return u * 2.0f * 3.14159274101257324e0f;
}

// side stream + events for graph branch parallelism (created once; no device memory)
struct SideStream {
    cudaStream_t s;
    cudaEvent_t fork, join;
    SideStream(){
        cudaStreamCreateWithFlags(&s, cudaStreamNonBlocking);
        cudaEventCreateWithFlags(&fork, cudaEventDisableTiming);
        cudaEventCreateWithFlags(&join, cudaEventDisableTiming);
    }
};
static SideStream& side(){ static SideStream x; return x; }

extern "C" void kernel_launch(void* const* d_in, const int* in_sizes, int n_in,
                              void* d_out, int out_size){
    const float* x    = (const float*)d_in[0];
    const float* xyz  = (const float*)d_in[1];
    const float* fpts = (const float*)d_in[2];
    const float* fpw  = (const float*)d_in[3];
    const float* m1_w0=(const float*)d_in[4],  *m1_b0=(const float*)d_in[5],
               * m1_g0=(const float*)d_in[6],  *m1_be0=(const float*)d_in[7];
    const float* m1_w1=(const float*)d_in[8],  *m1_b1=(const float*)d_in[9],
               * m1_g1=(const float*)d_in[10], *m1_be1=(const float*)d_in[11];
    const float* m1_w2=(const float*)d_in[12], *m1_b2=(const float*)d_in[13],
               * m1_g2=(const float*)d_in[14], *m1_be2=(const float*)d_in[15];
    const float* m2_w0=(const float*)d_in[16], *m2_b0=(const float*)d_in[17],
               * m2_g0=(const float*)d_in[18], *m2_be0=(const float*)d_in[19];
    const float* m2_w1=(const float*)d_in[20], *m2_b1=(const float*)d_in[21],
               * m2_g1=(const float*)d_in[22], *m2_be1=(const float*)d_in[23];
    const float* mr_w0=(const float*)d_in[24], *mr_b0=(const float*)d_in[25],
               * mr_g0=(const float*)d_in[26], *mr_be0=(const float*)d_in[27];
    const float* mr_w1=(const float*)d_in[28], *mr_b1=(const float*)d_in[29],
               * mr_g1=(const float*)d_in[30], *mr_be1=(const float*)d_in[31];
    float* out = (float*)d_out;

    float ang = jax_angle();
    float cc = (float)cos((double)ang);
    float sn = (float)sin((double)ang);

    SideStream& S = side();

    k_zero<<<1,256>>>();
    k_xsq<<<512,256>>>(x);
    // fork: m2 chain on side stream (data-disjoint from knn->p2 chain)
    cudaEventRecord(S.fork, 0);
    cudaStreamWaitEvent(S.s, S.fork, 0);
    k_m2g<<<dim3(8,64),256,0,S.s>>>(fpw, m2_w0);
    k_m2f<<<4,128,0,S.s>>>(m2_b0, m2_g0, m2_be0);
    k_m2b<<<1,512,0,S.s>>>(m2_w1, m2_b1, m2_g1, m2_be1);
    cudaEventRecord(S.join, S.s);
    // main chain
    k_knn<<<512,256>>>(x);
    k_sl<<<(NSL+255)/256,256>>>(xyz, fpts, cc, sn);
    k_p1<<<2048,256>>>(m1_w0, m1_b0);
    k_p2<<<2048,256>>>(m1_w0, m1_b0, m1_w1, m1_b1, m1_g0, m1_be0);
    // join before p3 (first consumer of g_w)
    cudaStreamWaitEvent(0, S.join, 0);
    k_p3<<<1024,256>>>(m1_w2, m1_b2, m1_g1, m1_be1);
    k_F<<<4096,256>>>(x, m1_g2, m1_be2);
    k_mr1<<<dim3(8,32),256>>>(mr_w0, mr_b0);
    k_foldmr<<<1,512>>>(mr_w1, mr_b1, mr_g0, mr_be0);
    k_mr2<<<64,256>>>();
    k_out<<<1024,256>>>(out, mr_g1, mr_be1);
}